// round 10
// baseline (speedup 1.0000x reference)
#include <cuda_runtime.h>
#include <float.h>

#define N_NODES 100000
#define N_EDGES 1200000
#define IN_F 128
#define HID 64
#define OUT_F 40
#define ELL_W 64

// ---------------- device scratch (no allocations allowed) ----------------
__device__ int   g_cur[N_NODES];                  // edge counters (= deg-1 after fill)
__device__ int   g_ell[(size_t)N_NODES * ELL_W];  // ELL neighbor table (src per dst)
__device__ int   g_is64;
__device__ float g_hs[(size_t)N_NODES * HID];     // dinv-prescaled transformed feats
__device__ float g_h1[(size_t)N_NODES * HID];     // layer-1 activations

// -------- init: zero cursors + detect edge dtype --------
__global__ void k_init(const long long* __restrict__ ei, int n) {
    int i = blockIdx.x * blockDim.x + threadIdx.x;
    if (i < n) g_cur[i] = 0;
    if (i == 0) {
        int ok = 1;
        #pragma unroll
        for (int j = 0; j < 16; j++) {
            long long v = ei[j];
            if (v < 0 || v >= n) ok = 0;
        }
        g_is64 = ok;
    }
}

// -------- fill ELL directly from the raw edge list --------
__global__ void k_fill(const void* __restrict__ ei, int e) {
    int i = blockIdx.x * blockDim.x + threadIdx.x;
    if (i < e) {
        int s, d;
        if (g_is64) {
            s = (int)((const long long*)ei)[i];
            d = (int)((const long long*)ei)[e + i];
        } else {
            s = ((const int*)ei)[i];
            d = ((const int*)ei)[e + i];
        }
        int pos = atomicAdd(&g_cur[d], 1);
        if (pos < ELL_W) g_ell[(size_t)d * ELL_W + pos] = s;
    }
}

// --- dense GEMM: g_hs[n,64] = (A[n,K] @ W[K,64]) * dinv[row] (prescaled) ---
// 64x64 tile per 256-thread block, 4x4 register blocking (proven shape).
// dinv computed inline from g_cur (deg = cur + 1 self-loop).
template <int K>
__global__ void k_gemm_hs(const float* __restrict__ A, const float* __restrict__ W, int n) {
    __shared__ __align__(16) float sW[64 * 64];
    __shared__ float sA[64 * 65];

    const int t = threadIdx.x;           // 256 threads
    const int row0 = blockIdx.x * 64;
    const int ty = t >> 4, tx = t & 15;  // 16x16 thread tile
    const int r0 = ty * 4, c0 = tx * 4;

    float acc[4][4] = {};

    for (int k0 = 0; k0 < K; k0 += 64) {
        __syncthreads();
        for (int i = t; i < 64 * 64 / 4; i += 256)
            ((float4*)sW)[i] = ((const float4*)(W + (size_t)k0 * 64))[i];
        for (int i = t; i < 64 * 16; i += 256) {
            int r = i >> 4;
            int kc = (i & 15) * 4;
            float4 v = make_float4(0.f, 0.f, 0.f, 0.f);
            if (row0 + r < n)
                v = *(const float4*)(A + (size_t)(row0 + r) * K + k0 + kc);
            float* d = &sA[r * 65 + kc];
            d[0] = v.x; d[1] = v.y; d[2] = v.z; d[3] = v.w;
        }
        __syncthreads();

        #pragma unroll 8
        for (int kk = 0; kk < 64; kk++) {
            float4 w4 = *(float4*)&sW[kk * 64 + c0];
            #pragma unroll
            for (int j = 0; j < 4; j++) {
                float a = sA[(r0 + j) * 65 + kk];
                acc[j][0] += a * w4.x;
                acc[j][1] += a * w4.y;
                acc[j][2] += a * w4.z;
                acc[j][3] += a * w4.w;
            }
        }
    }

    #pragma unroll
    for (int j = 0; j < 4; j++) {
        int r = row0 + r0 + j;
        if (r < n) {
            float dv = rsqrtf((float)(g_cur[r] + 1));
            *(float4*)&g_hs[(size_t)r * 64 + c0] =
                make_float4(acc[j][0] * dv, acc[j][1] * dv,
                            acc[j][2] * dv, acc[j][3] * dv);
        }
    }
}

// agg: out[v] = act(dinv[v]*(hs[v] + sum_{dst=v} hs[src]) + b)  [hs prescaled]
// one warp per node; lane owns float2; broadcast idx loads from ELL row.
// Batch depth 8 -> 4 -> 1 (R9-proven shape).
__global__ void k_agg(const float* __restrict__ b, float* __restrict__ out,
                      int n, int do_relu) {
    int gw = (blockIdx.x * blockDim.x + threadIdx.x) >> 5;
    int lane = threadIdx.x & 31;
    if (gw >= n) return;

    int cnt0 = g_cur[gw];
    int cnt = (cnt0 < ELL_W) ? cnt0 : ELL_W;
    const int* row = g_ell + (size_t)gw * ELL_W;

    float2 acc = *(const float2*)(g_hs + (size_t)gw * 64 + 2 * lane);
    float ax = acc.x, ay = acc.y;
    float bx = 0.f, by = 0.f;

    int j = 0;
    for (; j + 8 <= cnt; j += 8) {
        int s0 = row[j];
        int s1 = row[j + 1];
        int s2 = row[j + 2];
        int s3 = row[j + 3];
        int s4 = row[j + 4];
        int s5 = row[j + 5];
        int s6 = row[j + 6];
        int s7 = row[j + 7];
        float2 v0 = *(const float2*)(g_hs + (size_t)s0 * 64 + 2 * lane);
        float2 v1 = *(const float2*)(g_hs + (size_t)s1 * 64 + 2 * lane);
        float2 v2 = *(const float2*)(g_hs + (size_t)s2 * 64 + 2 * lane);
        float2 v3 = *(const float2*)(g_hs + (size_t)s3 * 64 + 2 * lane);
        float2 v4 = *(const float2*)(g_hs + (size_t)s4 * 64 + 2 * lane);
        float2 v5 = *(const float2*)(g_hs + (size_t)s5 * 64 + 2 * lane);
        float2 v6 = *(const float2*)(g_hs + (size_t)s6 * 64 + 2 * lane);
        float2 v7 = *(const float2*)(g_hs + (size_t)s7 * 64 + 2 * lane);
        ax += (v0.x + v1.x) + (v2.x + v3.x);
        bx += (v4.x + v5.x) + (v6.x + v7.x);
        ay += (v0.y + v1.y) + (v2.y + v3.y);
        by += (v4.y + v5.y) + (v6.y + v7.y);
    }
    if (j + 4 <= cnt) {
        int s0 = row[j];
        int s1 = row[j + 1];
        int s2 = row[j + 2];
        int s3 = row[j + 3];
        float2 v0 = *(const float2*)(g_hs + (size_t)s0 * 64 + 2 * lane);
        float2 v1 = *(const float2*)(g_hs + (size_t)s1 * 64 + 2 * lane);
        float2 v2 = *(const float2*)(g_hs + (size_t)s2 * 64 + 2 * lane);
        float2 v3 = *(const float2*)(g_hs + (size_t)s3 * 64 + 2 * lane);
        ax += (v0.x + v1.x) + (v2.x + v3.x);
        ay += (v0.y + v1.y) + (v2.y + v3.y);
        j += 4;
    }
    for (; j < cnt; j++) {
        int s = row[j];
        float2 v = *(const float2*)(g_hs + (size_t)s * 64 + 2 * lane);
        bx += v.x;
        by += v.y;
    }
    ax += bx;
    ay += by;

    float dv = rsqrtf((float)(cnt0 + 1));
    float vx = ax * dv + b[2 * lane];
    float vy = ay * dv + b[2 * lane + 1];
    if (do_relu) { vx = fmaxf(vx, 0.f); vy = fmaxf(vy, 0.f); }
    *(float2*)(out + (size_t)gw * 64 + 2 * lane) = make_float2(vx, vy);
}

// ------------- head: logits = emb @ Wc + bc, softmax, argmax -------------
// one warp per node, 16 nodes per 512-thread block.
__global__ void __launch_bounds__(512) k_head(const float* __restrict__ emb,
                       const float* __restrict__ Wc,
                       const float* __restrict__ bc, float* __restrict__ logits,
                       float* __restrict__ soft, float* __restrict__ hard, int n) {
    __shared__ float sW[64 * OUT_F];
    __shared__ float sb[OUT_F];
    __shared__ float sE[16][64];

    int t = threadIdx.x;
    for (int i = t; i < 64 * OUT_F; i += 512) sW[i] = Wc[i];
    if (t < OUT_F) sb[t] = bc[t];

    int w = t >> 5, lane = t & 31;
    int node = blockIdx.x * 16 + w;
    if (node < n) {
        sE[w][lane]      = emb[(size_t)node * 64 + lane];
        sE[w][lane + 32] = emb[(size_t)node * 64 + lane + 32];
    }
    __syncthreads();
    if (node >= n) return;

    float acc0 = sb[lane];
    float acc1 = (lane < 8) ? sb[lane + 32] : 0.f;
    #pragma unroll 8
    for (int k = 0; k < 64; k++) {
        float e = sE[w][k];
        acc0 += e * sW[k * OUT_F + lane];
        if (lane < 8) acc1 += e * sW[k * OUT_F + lane + 32];
    }

    logits[(size_t)node * OUT_F + lane] = acc0;
    if (lane < 8) logits[(size_t)node * OUT_F + lane + 32] = acc1;

    float m = fmaxf(acc0, (lane < 8) ? acc1 : -FLT_MAX);
    #pragma unroll
    for (int o = 16; o > 0; o >>= 1) m = fmaxf(m, __shfl_xor_sync(0xffffffffu, m, o));
    float e0 = __expf(acc0 - m);
    float e1 = (lane < 8) ? __expf(acc1 - m) : 0.f;
    float s = e0 + e1;
    #pragma unroll
    for (int o = 16; o > 0; o >>= 1) s += __shfl_xor_sync(0xffffffffu, s, o);
    float inv = 1.f / s;
    soft[(size_t)node * OUT_F + lane] = e0 * inv;
    if (lane < 8) soft[(size_t)node * OUT_F + lane + 32] = e1 * inv;

    int cand = 0x7fffffff;
    if (acc0 == m) cand = lane;
    if (lane < 8 && acc1 == m) cand = min(cand, lane + 32);
    #pragma unroll
    for (int o = 16; o > 0; o >>= 1) cand = min(cand, __shfl_xor_sync(0xffffffffu, cand, o));
    if (lane == 0) hard[node] = (float)cand;
}

extern "C" void kernel_launch(void* const* d_in, const int* in_sizes, int n_in,
                              void* d_out, int out_size) {
    const float* x  = (const float*)d_in[0];
    const void*  ei = d_in[1];
    const float* W1 = (const float*)d_in[2];
    const float* b1 = (const float*)d_in[3];
    const float* W2 = (const float*)d_in[4];
    const float* b2 = (const float*)d_in[5];
    const float* Wc = (const float*)d_in[6];
    const float* bc = (const float*)d_in[7];

    const int N = in_sizes[0] / IN_F;
    const int E = in_sizes[1] / 2;

    float* outp   = (float*)d_out;
    float* logits = outp;
    float* emb    = outp + (size_t)N * OUT_F;
    float* soft   = emb  + (size_t)N * HID;
    float* hard   = soft + (size_t)N * OUT_F;

    const int TB = 256;

    k_init<<<(N + TB - 1) / TB, TB>>>((const long long*)ei, N);     // 1
    k_fill<<<(E + TB - 1) / TB, TB>>>(ei, E);                       // 2
    k_gemm_hs<IN_F><<<(N + 63) / 64, 256>>>(x, W1, N);              // 3
    k_agg<<<((N * 32) + TB - 1) / TB, TB>>>(b1, g_h1, N, 1);        // 4  <- PROFILED
    k_gemm_hs<HID><<<(N + 63) / 64, 256>>>(g_h1, W2, N);            // 5
    k_agg<<<((N * 32) + TB - 1) / TB, TB>>>(b2, emb, N, 0);         // 6
    k_head<<<(N + 15) / 16, 512>>>(emb, Wc, bc, logits, soft, hard, N);  // 7
}

// round 12
// speedup vs baseline: 1.1854x; 1.1854x over previous
#include <cuda_runtime.h>
#include <cstdint>
#include <float.h>

#define N_NODES 100000
#define N_EDGES 1200000
#define IN_F 128
#define HID 64
#define OUT_F 40
#define ELL_W 64
#define CHUNK 16

// ---------------- device scratch (no allocations allowed) ----------------
__device__ int   g_cur[N_NODES];                  // edge counters (= deg-1 after fill)
__device__ int   g_ell[(size_t)N_NODES * ELL_W];  // ELL neighbor table (src per dst)
__device__ int   g_is64;
__device__ float g_hs[(size_t)N_NODES * HID];     // dinv-prescaled transformed feats
__device__ float g_h1[(size_t)N_NODES * HID];     // layer-1 activations

// -------- init: zero cursors + detect edge dtype --------
__global__ void k_init(const long long* __restrict__ ei, int n) {
    int i = blockIdx.x * blockDim.x + threadIdx.x;
    if (i < n) g_cur[i] = 0;
    if (i == 0) {
        int ok = 1;
        #pragma unroll
        for (int j = 0; j < 16; j++) {
            long long v = ei[j];
            if (v < 0 || v >= n) ok = 0;
        }
        g_is64 = ok;
    }
}

// -------- fill ELL directly from the raw edge list --------
__global__ void k_fill(const void* __restrict__ ei, int e) {
    int i = blockIdx.x * blockDim.x + threadIdx.x;
    if (i < e) {
        int s, d;
        if (g_is64) {
            s = (int)((const long long*)ei)[i];
            d = (int)((const long long*)ei)[e + i];
        } else {
            s = ((const int*)ei)[i];
            d = ((const int*)ei)[e + i];
        }
        int pos = atomicAdd(&g_cur[d], 1);
        if (pos < ELL_W) g_ell[(size_t)d * ELL_W + pos] = s;
    }
}

// --- dense GEMM: g_hs[n,64] = (A[n,K] @ W[K,64]) * dinv[row] (prescaled) ---
// dinv computed inline from g_cur (deg = cur + 1 self-loop).
template <int K>
__global__ void k_gemm_hs(const float* __restrict__ A, const float* __restrict__ W, int n) {
    __shared__ __align__(16) float sW[64 * 64];
    __shared__ float sA[64 * 65];

    const int t = threadIdx.x;           // 256 threads
    const int row0 = blockIdx.x * 64;
    const int ty = t >> 4, tx = t & 15;  // 16x16 thread tile
    const int r0 = ty * 4, c0 = tx * 4;

    float acc[4][4] = {};

    for (int k0 = 0; k0 < K; k0 += 64) {
        __syncthreads();
        for (int i = t; i < 64 * 64 / 4; i += 256)
            ((float4*)sW)[i] = ((const float4*)(W + (size_t)k0 * 64))[i];
        for (int i = t; i < 64 * 16; i += 256) {
            int r = i >> 4;
            int kc = (i & 15) * 4;
            float4 v = make_float4(0.f, 0.f, 0.f, 0.f);
            if (row0 + r < n)
                v = *(const float4*)(A + (size_t)(row0 + r) * K + k0 + kc);
            float* d = &sA[r * 65 + kc];
            d[0] = v.x; d[1] = v.y; d[2] = v.z; d[3] = v.w;
        }
        __syncthreads();

        #pragma unroll 8
        for (int kk = 0; kk < 64; kk++) {
            float4 w4 = *(float4*)&sW[kk * 64 + c0];
            #pragma unroll
            for (int j = 0; j < 4; j++) {
                float a = sA[(r0 + j) * 65 + kk];
                acc[j][0] += a * w4.x;
                acc[j][1] += a * w4.y;
                acc[j][2] += a * w4.z;
                acc[j][3] += a * w4.w;
            }
        }
    }

    #pragma unroll
    for (int j = 0; j < 4; j++) {
        int r = row0 + r0 + j;
        if (r < n) {
            float dv = rsqrtf((float)(g_cur[r] + 1));
            *(float4*)&g_hs[(size_t)r * 64 + c0] =
                make_float4(acc[j][0] * dv, acc[j][1] * dv,
                            acc[j][2] * dv, acc[j][3] * dv);
        }
    }
}

// agg v3: out[v] = act(dinv[v]*(hs[v] + sum hs[src]) + b)   [hs prescaled]
// one warp per node; lane owns float2. Neighbor rows staged into SHARED via
// cp.async (no dest registers -> true MLP=CHUNK regardless of regalloc),
// then accumulated from shared. Each lane copies & reads only its own 8B
// slice of every row, so cp.async.wait_group alone orders it.
__global__ void __launch_bounds__(256) k_agg(const float* __restrict__ b,
                                             float* __restrict__ out,
                                             int n, int do_relu) {
    __shared__ __align__(16) float sbuf[8][CHUNK * 64];   // 4KB per warp, 32KB total

    int gw = (blockIdx.x * blockDim.x + threadIdx.x) >> 5;
    int wslot = threadIdx.x >> 5;        // warp within block (0..7)
    int lane = threadIdx.x & 31;
    if (gw >= n) return;

    int cnt0 = g_cur[gw];
    int cnt = (cnt0 < ELL_W) ? cnt0 : ELL_W;
    const int* row = g_ell + (size_t)gw * ELL_W;

    float2 a = *(const float2*)(g_hs + (size_t)gw * 64 + 2 * lane);
    float* sw = &sbuf[wslot][0];
    unsigned int sw_u32 = (unsigned int)__cvta_generic_to_shared(sw) + 8 * lane;

    for (int base = 0; base < cnt; base += CHUNK) {
        int m = min(CHUNK, cnt - base);
        int idx = (lane < m) ? row[base + lane] : 0;   // coalesced idx batch

        for (int i = 0; i < m; i++) {
            int s = __shfl_sync(0xffffffffu, idx, i);
            const float* src = g_hs + (size_t)s * 64 + 2 * lane;
            unsigned int dst = sw_u32 + i * 256;
            asm volatile("cp.async.ca.shared.global [%0], [%1], 8;"
                         :: "r"(dst), "l"(src) : "memory");
        }
        asm volatile("cp.async.commit_group;" ::: "memory");
        asm volatile("cp.async.wait_group 0;" ::: "memory");

        for (int i = 0; i < m; i++) {
            float2 v = *(const float2*)(sw + i * 64 + 2 * lane);
            a.x += v.x;
            a.y += v.y;
        }
    }

    float dv = rsqrtf((float)(cnt0 + 1));
    float vx = a.x * dv + b[2 * lane];
    float vy = a.y * dv + b[2 * lane + 1];
    if (do_relu) { vx = fmaxf(vx, 0.f); vy = fmaxf(vy, 0.f); }
    *(float2*)(out + (size_t)gw * 64 + 2 * lane) = make_float2(vx, vy);
}

// ------------- head: logits = emb @ Wc + bc, softmax, argmax -------------
// one warp per node, 16 nodes per 512-thread block.
__global__ void __launch_bounds__(512) k_head(const float* __restrict__ emb,
                       const float* __restrict__ Wc,
                       const float* __restrict__ bc, float* __restrict__ logits,
                       float* __restrict__ soft, float* __restrict__ hard, int n) {
    __shared__ float sW[64 * OUT_F];
    __shared__ float sb[OUT_F];
    __shared__ float sE[16][64];

    int t = threadIdx.x;
    for (int i = t; i < 64 * OUT_F; i += 512) sW[i] = Wc[i];
    if (t < OUT_F) sb[t] = bc[t];

    int w = t >> 5, lane = t & 31;
    int node = blockIdx.x * 16 + w;
    if (node < n) {
        sE[w][lane]      = emb[(size_t)node * 64 + lane];
        sE[w][lane + 32] = emb[(size_t)node * 64 + lane + 32];
    }
    __syncthreads();
    if (node >= n) return;

    float acc0 = sb[lane];
    float acc1 = (lane < 8) ? sb[lane + 32] : 0.f;
    #pragma unroll 8
    for (int k = 0; k < 64; k++) {
        float e = sE[w][k];
        acc0 += e * sW[k * OUT_F + lane];
        if (lane < 8) acc1 += e * sW[k * OUT_F + lane + 32];
    }

    logits[(size_t)node * OUT_F + lane] = acc0;
    if (lane < 8) logits[(size_t)node * OUT_F + lane + 32] = acc1;

    float m = fmaxf(acc0, (lane < 8) ? acc1 : -FLT_MAX);
    #pragma unroll
    for (int o = 16; o > 0; o >>= 1) m = fmaxf(m, __shfl_xor_sync(0xffffffffu, m, o));
    float e0 = __expf(acc0 - m);
    float e1 = (lane < 8) ? __expf(acc1 - m) : 0.f;
    float s = e0 + e1;
    #pragma unroll
    for (int o = 16; o > 0; o >>= 1) s += __shfl_xor_sync(0xffffffffu, s, o);
    float inv = 1.f / s;
    soft[(size_t)node * OUT_F + lane] = e0 * inv;
    if (lane < 8) soft[(size_t)node * OUT_F + lane + 32] = e1 * inv;

    int cand = 0x7fffffff;
    if (acc0 == m) cand = lane;
    if (lane < 8 && acc1 == m) cand = min(cand, lane + 32);
    #pragma unroll
    for (int o = 16; o > 0; o >>= 1) cand = min(cand, __shfl_xor_sync(0xffffffffu, cand, o));
    if (lane == 0) hard[node] = (float)cand;
}

extern "C" void kernel_launch(void* const* d_in, const int* in_sizes, int n_in,
                              void* d_out, int out_size) {
    const float* x  = (const float*)d_in[0];
    const void*  ei = d_in[1];
    const float* W1 = (const float*)d_in[2];
    const float* b1 = (const float*)d_in[3];
    const float* W2 = (const float*)d_in[4];
    const float* b2 = (const float*)d_in[5];
    const float* Wc = (const float*)d_in[6];
    const float* bc = (const float*)d_in[7];

    const int N = in_sizes[0] / IN_F;
    const int E = in_sizes[1] / 2;

    float* outp   = (float*)d_out;
    float* logits = outp;
    float* emb    = outp + (size_t)N * OUT_F;
    float* soft   = emb  + (size_t)N * HID;
    float* hard   = soft + (size_t)N * OUT_F;

    const int TB = 256;

    k_init<<<(N + TB - 1) / TB, TB>>>((const long long*)ei, N);     // 1
    k_fill<<<(E + TB - 1) / TB, TB>>>(ei, E);                       // 2
    k_gemm_hs<IN_F><<<(N + 63) / 64, 256>>>(x, W1, N);              // 3
    k_agg<<<((N * 32) + TB - 1) / TB, TB>>>(b1, g_h1, N, 1);        // 4  <- PROFILED
    k_gemm_hs<HID><<<(N + 63) / 64, 256>>>(g_h1, W2, N);            // 5
    k_agg<<<((N * 32) + TB - 1) / TB, TB>>>(b2, emb, N, 0);         // 6
    k_head<<<(N + 15) / 16, 512>>>(emb, Wc, bc, logits, soft, hard, N);  // 7
}